// round 4
// baseline (speedup 1.0000x reference)
#include <cuda_runtime.h>
#include <math.h>

#define T_LEN 512
#define B_SZ  64
#define D_SZ  1024
#define H_SZ  512
#define L_SZ  5

#define NCTA 128
#define NTHR 256
#define NBAR_PER_LAUNCH 6000u

typedef unsigned long long ull;

// ---------------- device-global scratch (no allocation allowed) ----------------
__device__ float    g_XHt[T_LEN * H_SZ * B_SZ];   // [t][j][b]
__device__ float    g_XCt[T_LEN * H_SZ * B_SZ];   // [t][j][b]
__device__ float    g_h[2][H_SZ * B_SZ];          // hidden double buffer [j][b]
__device__ unsigned g_flags[NCTA];                // per-CTA monotonic barrier flags
__device__ unsigned g_cur  = 0;                   // generation base for this launch
__device__ unsigned g_next = 0;

__global__ void bump_kernel() {
    unsigned b = g_next;
    g_cur  = b;
    g_next = b + NBAR_PER_LAUNCH;
}

// packed fp32x2 FMA
__device__ __forceinline__ ull fma2(ull a, ull b, ull c) {
    ull d;
    asm("fma.rn.f32x2 %0, %1, %2, %3;" : "=l"(d) : "l"(a), "l"(b), "l"(c));
    return d;
}
union UF2 { ull u; float2 f; };

// ---------------- grid barrier: per-CTA flags, release/acquire, monotonic gens --
__device__ __forceinline__ void gbar(int tid, int cta, unsigned gen) {
    __syncthreads();
    if (tid == 0) {
        __threadfence();   // release all CTA writes (canonical syncthreads+fence)
        asm volatile("st.release.gpu.global.u32 [%0], %1;"
                     :: "l"(&g_flags[cta]), "r"(gen) : "memory");
    }
    if (tid < NCTA) {
        unsigned v;
        do {
            asm volatile("ld.acquire.gpu.global.u32 %0, [%1];"
                         : "=r"(v) : "l"(&g_flags[tid]) : "memory");
        } while ((int)(v - gen) < 0);
    }
    __syncthreads();
}

// ---------------- precompute: XHt/XCt[t][j][b] = x[t,b,:]@W[:,j] + bias[j] ------
__global__ void __launch_bounds__(NTHR) proj_kernel(
    const float* __restrict__ x,
    const float* __restrict__ Ww,
    const float* __restrict__ Wb,
    const int gate)
{
    __shared__ float As[32][128];
    __shared__ float Bs[32][64];
    float* __restrict__ dst = gate ? g_XCt : g_XHt;

    const int tid = threadIdx.x;
    const int bm  = blockIdx.x * 128;
    const int bn  = blockIdx.y * 64;
    const int tm  = tid & 15;
    const int tn  = tid >> 4;

    float acc[8][4];
#pragma unroll
    for (int i = 0; i < 8; i++)
#pragma unroll
        for (int j = 0; j < 4; j++) acc[i][j] = 0.0f;

    for (int k0 = 0; k0 < D_SZ; k0 += 32) {
#pragma unroll
        for (int r = 0; r < 4; r++) {
            int lin = tid + r * 256;
            int m = lin >> 3, kq = lin & 7;
            float4 v = *(const float4*)(x + (size_t)(bm + m) * D_SZ + k0 + kq * 4);
            As[kq * 4 + 0][m] = v.x;
            As[kq * 4 + 1][m] = v.y;
            As[kq * 4 + 2][m] = v.z;
            As[kq * 4 + 3][m] = v.w;
        }
#pragma unroll
        for (int r = 0; r < 2; r++) {
            int lin = tid + r * 256;
            int kk = lin >> 4, jq = lin & 15;
            *(float4*)&Bs[kk][jq * 4] =
                *(const float4*)(Ww + (size_t)(k0 + kk) * H_SZ + bn + jq * 4);
        }
        __syncthreads();
#pragma unroll
        for (int k = 0; k < 32; k++) {
            float4 a0 = *(const float4*)&As[k][tm * 4];
            float4 a1 = *(const float4*)&As[k][64 + tm * 4];
            float4 bv = *(const float4*)&Bs[k][tn * 4];
            float av[8] = {a0.x, a0.y, a0.z, a0.w, a1.x, a1.y, a1.z, a1.w};
            float bw[4] = {bv.x, bv.y, bv.z, bv.w};
#pragma unroll
            for (int i = 0; i < 8; i++)
#pragma unroll
                for (int j = 0; j < 4; j++)
                    acc[i][j] = fmaf(av[i], bw[j], acc[i][j]);
        }
        __syncthreads();
    }

#pragma unroll
    for (int i = 0; i < 8; i++) {
        int m = bm + ((i < 4) ? (tm * 4 + i) : (64 + tm * 4 + i - 4));
        int t = m >> 6, b = m & 63;
#pragma unroll
        for (int j = 0; j < 4; j++) {
            int jj = bn + tn * 4 + j;
            dst[(size_t)t * (H_SZ * B_SZ) + (size_t)jj * B_SZ + b] = acc[i][j] + Wb[jj];
        }
    }
}

// ---------------- persistent sequential kernel --------------------------------
// 128 CTAs = 64 j-groups (8 j each) x 2 b-halves (32 b each). Full K per CTA,
// split 4-ways across thread quarters; smem reduce; ONE grid barrier per layer.
__global__ void __launch_bounds__(NTHR, 1) rhn_seq_kernel(
    const float* __restrict__ RHw, const float* __restrict__ RHb,
    const float* __restrict__ RCw, const float* __restrict__ RCb,
    float* __restrict__ out)
{
    __shared__ __align__(16) float  hs[4][16][32];     // [q][k][b] chunk (8 KB)
    __shared__ __align__(16) float2 rdup[4][2][16][8]; // [q][g][k][j] dup pairs (8 KB)
    __shared__ __align__(16) float  red[4][64][8];     // partials [q][r][f] (8 KB)

    const int tid = threadIdx.x;
    const int cta = blockIdx.x;
    const unsigned base = __ldcg(&g_cur);
    unsigned bar = 0;

    const int j0 = (cta >> 1) * 8;
    const int b0 = (cta & 1) * 32;

    // phase-A compute mapping: quarter q, within quarter: gate/jp/bq (gate warp-uniform)
    const int q    = tid >> 6;
    const int r    = tid & 63;
    const int gate = r >> 5;
    const int s    = r & 31;
    const int jp   = s >> 3;        // thread's j = j0 + jp*2 + {0,1}
    const int bq   = s & 7;         // thread's b = b0 + bq*4 + {0..3}

    // hs staging: thread loads 2 consecutive float4 of g_h rows
    const int hrow  = tid >> 2;                    // 0..63 -> (q, k16)
    const int hoff  = ((hrow >> 4) * 128 + (hrow & 15)) * B_SZ + b0 + ((tid * 2) & 7) * 4;
    // rdup staging: (sg, sq, sk, sjh)
    const int sg  = tid >> 7;
    const int sr  = (tid >> 1) & 63;
    const int sq  = sr >> 4;
    const int sk  = sr & 15;
    const int sjh = tid & 1;
    const int roff = (sq * 128 + sk) * H_SZ + j0 + sjh * 4;

    // phase-B mapping: one (j,b) element per thread
    const int jl = tid >> 5;        // 0..7
    const int bl = tid & 31;        // 0..31
    const int fE  = (jl & 1) * 4 + (bl & 3);
    const int rE0 = (jl >> 1) * 8 + (bl >> 2);
    const int rE1 = 32 + rE0;
    const int eg  = (j0 + jl) * B_SZ + b0 + bl;    // global [j][b] index

    // h0 = 0
    __stcg(&g_h[0][cta * NTHR + tid], 0.0f);
    gbar(tid, cta, base + (++bar));

    int p = 0;
    for (int pass = 0; pass < 2; pass++)
    for (int t = 0; t < T_LEN; t++)
    for (int l = 0; l < L_SZ; l++) {
        const float* __restrict__ hp = g_h[p];
        const size_t lbase = (size_t)l * H_SZ * H_SZ;
        const float* __restrict__ Rsel = (sg ? RCw : RHw) + lbase;

        // early prefetch of phase-B operands (long-latency, hidden under phase A)
        float hold = __ldcg(hp + eg);
        float xh = 0.0f, xc = 0.0f;
        if (l == 0) {
            xh = __ldcg(&g_XHt[(size_t)t * (H_SZ * B_SZ) + eg]);
            xc = __ldcg(&g_XCt[(size_t)t * (H_SZ * B_SZ) + eg]);
        }

        ull a0 = 0ull, a1 = 0ull, a2 = 0ull, a3 = 0ull;

        // prefetch chunk 0
        float4 ph0, ph1, pr;
        {
            const float* sA = hp + hoff;
            ph0 = __ldcg((const float4*)sA);
            ph1 = __ldcg((const float4*)(sA + 4));
            pr  = *(const float4*)(Rsel + roff);
        }
#pragma unroll
        for (int c = 0; c < 8; c++) {
            __syncthreads();
            ((float4*)hs)[tid * 2]     = ph0;
            ((float4*)hs)[tid * 2 + 1] = ph1;
            *(float4*)&rdup[sq][sg][sk][sjh * 4]     = make_float4(pr.x, pr.x, pr.y, pr.y);
            *(float4*)&rdup[sq][sg][sk][sjh * 4 + 2] = make_float4(pr.z, pr.z, pr.w, pr.w);
            __syncthreads();
            if (c < 7) {
                const int kb = (c + 1) * 16;
                const float* sA = hp + hoff + kb * B_SZ;
                ph0 = __ldcg((const float4*)sA);
                ph1 = __ldcg((const float4*)(sA + 4));
                pr  = *(const float4*)(Rsel + roff + (size_t)kb * H_SZ);
            }
#pragma unroll
            for (int kk = 0; kk < 16; kk++) {
                const ulonglong2 hv = *(const ulonglong2*)&hs[q][kk][bq * 4];
                const ulonglong2 rv = *(const ulonglong2*)&rdup[q][gate][kk][jp * 2];
                a0 = fma2(hv.x, rv.x, a0);   // j_even, b01
                a1 = fma2(hv.y, rv.x, a1);   // j_even, b23
                a2 = fma2(hv.x, rv.y, a2);   // j_odd,  b01
                a3 = fma2(hv.y, rv.y, a3);   // j_odd,  b23
            }
        }
        {
            UF2 u0, u1, u2, u3;
            u0.u = a0; u1.u = a1; u2.u = a2; u3.u = a3;
            *(float4*)&red[q][r][0] = make_float4(u0.f.x, u0.f.y, u1.f.x, u1.f.y);
            *(float4*)&red[q][r][4] = make_float4(u2.f.x, u2.f.y, u3.f.x, u3.f.y);
        }
        __syncthreads();

        // ---- phase B: reduce quarters + bias (+X at l==0) + highway combine ----
        {
            float sH = red[0][rE0][fE] + red[1][rE0][fE]
                     + red[2][rE0][fE] + red[3][rE0][fE];
            float sC = red[0][rE1][fE] + red[1][rE1][fE]
                     + red[2][rE1][fE] + red[3][rE1][fE];
            sH += RHb[l * H_SZ + j0 + jl];
            sC += RCb[l * H_SZ + j0 + jl];
            if (l == 0) { sH += xh; sC += xc; }
            float hl = tanhf(sH);
            float tl = 1.0f / (1.0f + __expf(-sC));
            float hn = fmaf(tl, hl - hold, hold);
            __stcg(&g_h[p ^ 1][eg], hn);
            if (l == L_SZ - 1) {
                size_t o = (size_t)t * (B_SZ * 2 * H_SZ)
                         + (size_t)(b0 + bl) * (2 * H_SZ)
                         + (size_t)pass * H_SZ + j0 + jl;
                out[o] = hn;
                if (t == T_LEN - 1) {
                    out[(size_t)T_LEN * (B_SZ * 2 * H_SZ)
                        + (size_t)(b0 + bl) * (2 * H_SZ)
                        + (size_t)pass * H_SZ + j0 + jl] = hn;
                }
            }
        }
        gbar(tid, cta, base + (++bar));
        p ^= 1;
    }
}

extern "C" void kernel_launch(void* const* d_in, const int* in_sizes, int n_in,
                              void* d_out, int out_size)
{
    const float* x   = (const float*)d_in[0];
    const float* WHw = (const float*)d_in[1];
    const float* WHb = (const float*)d_in[2];
    const float* WCw = (const float*)d_in[3];
    const float* WCb = (const float*)d_in[4];
    const float* RHw = (const float*)d_in[5];
    const float* RHb = (const float*)d_in[6];
    const float* RCw = (const float*)d_in[7];
    const float* RCb = (const float*)d_in[8];
    float* out = (float*)d_out;

    bump_kernel<<<1, 1>>>();
    dim3 pg(256, 8);
    proj_kernel<<<pg, NTHR>>>(x, WHw, WHb, 0);
    proj_kernel<<<pg, NTHR>>>(x, WCw, WCb, 1);
    rhn_seq_kernel<<<NCTA, NTHR>>>(RHw, RHb, RCw, RCb, out);
}